// round 14
// baseline (speedup 1.0000x reference)
#include <cuda_runtime.h>
#include <cstdint>
#include <cstddef>

#define N_NODES 100000
#define MPAD    100096            // 782 * 128
#define MTILES  782
#define N_EDGES 600000
#define DIM_D 128
#define DIM_H 256
#define GEMM_GRID 296             // 2 CTAs per SM, persistent

// ---------------- scratch (device globals: no allocation allowed) ----------
__device__ __align__(256) float g_H0[(size_t)MPAD * DIM_D];   // h (agg, f32); reused as X2
__device__ __align__(256) float g_X1[(size_t)MPAD * DIM_H];   // layer-1 raw output (f32)
__device__ __align__(256) uint32_t g_W1t[DIM_H * DIM_D];      // tf32 weights
__device__ __align__(256) uint32_t g_W2t[DIM_D * DIM_H];
__device__ float g_sum1[DIM_H];
__device__ float g_sq1[DIM_H];
__device__ float g_sum2[DIM_D];
__device__ float g_sq2[DIM_D];
__device__ float g_s1[DIM_H];
__device__ float g_t1[DIM_H];
__device__ float g_s2[DIM_D];
__device__ float g_t2[DIM_D];

__device__ __forceinline__ uint32_t f2tf32(float x) {
    uint32_t r;
    asm("cvt.rna.tf32.f32 %0, %1;" : "=r"(r) : "f"(x));
    return r;
}

// ---------------- graph aggregation ----------------------------------------

// H0[n,:] = (1 + eps - degree[n]) * node_rep[n,:]; pad rows = 0; zero stats;
// also converts both weight matrices to tf32 (folded in: saves a launch).
__global__ void k_init(const float* __restrict__ nr,
                       const float* __restrict__ deg,
                       const float* __restrict__ eps,
                       const float* __restrict__ W1,
                       const float* __restrict__ W2) {
    int gidx = blockIdx.x * blockDim.x + threadIdx.x;
    if (blockIdx.x == 0) {
        int t = threadIdx.x;
        if (t < DIM_H) { g_sum1[t] = 0.f; g_sq1[t] = 0.f; }
        if (t < DIM_D) { g_sum2[t] = 0.f; g_sq2[t] = 0.f; }
    }
    if (gidx < DIM_H * DIM_D) {
        g_W1t[gidx] = f2tf32(W1[gidx]);
        g_W2t[gidx] = f2tf32(W2[gidx]);
    }
    if (gidx >= MPAD * (DIM_D / 4)) return;
    int row = gidx >> 5;                               // 32 float4 per row
    float4 o = make_float4(0.f, 0.f, 0.f, 0.f);
    if (row < N_NODES) {
        float c = 1.0f + eps[0] - deg[row];
        float4 v = reinterpret_cast<const float4*>(nr)[gidx];
        o = make_float4(c * v.x, c * v.y, c * v.z, c * v.w);
    }
    reinterpret_cast<float4*>(g_H0)[gidx] = o;
}

__device__ __forceinline__ void red_add_v4(float* addr, float4 v) {
    asm volatile("red.global.add.v4.f32 [%0], {%1,%2,%3,%4};"
                 :: "l"(addr), "f"(v.x), "f"(v.y), "f"(v.z), "f"(v.w)
                 : "memory");
}

// one warp per edge: m = nr[src]+nr[dst]+ea; scatter-add to both endpoints.
__global__ void k_edge_scatter(const float* __restrict__ nr,
                               const float* __restrict__ ea,
                               const int* __restrict__ src,
                               const int* __restrict__ dst) {
    int e = blockIdx.x * 8 + (threadIdx.x >> 5);
    if (e >= N_EDGES) return;
    int lane = threadIdx.x & 31;
    int s = src[e];
    int d = dst[e];
    float4 a = __ldg(reinterpret_cast<const float4*>(nr + (size_t)s * DIM_D) + lane);
    float4 b = __ldg(reinterpret_cast<const float4*>(nr + (size_t)d * DIM_D) + lane);
    float4 c = __ldcs(reinterpret_cast<const float4*>(ea + (size_t)e * DIM_D) + lane);
    float4 m = make_float4(a.x + b.x + c.x, a.y + b.y + c.y,
                           a.z + b.z + c.z, a.w + b.w + c.w);
    red_add_v4(g_H0 + (size_t)s * DIM_D + lane * 4, m);
    red_add_v4(g_H0 + (size_t)d * DIM_D + lane * 4, m);
}

// ---------------- persistent flat-stream tf32 GEMM --------------------------
// C[m,n] = sum_k A[m,k] * B[n,k].  Grid = 296 (2 CTA/SM), persistent.
// Flat stream over (block-tile, k-tile): the 3-stage cp.async ring fills ONCE
// per CTA and never drains across block-tiles (this is what R8's wave-launched
// version paid 5.3x for). n-fastest tile order -> concurrent CTAs share A rows
// in L2. A raw f32 via cp.async; each thread converts in-smem the exact words
// its own cp.async staged (self-visibility via wait_group). BN==true applies
// y=relu(x*s+t) and zeroes pad rows. ONE __syncthreads per k-tile:
//   wait_group 1 -> cvt(own words) -> barrier -> issue(t+2) -> mma
// (the barrier retires all readers of stage (t-1)%3 == (t+2)%3 before reuse).
// Per-block-tile epilogue (after last k-tile): store C + fused column
// sum/sumsq atomics; register-local, overlaps the next tile's async loads.

#define GSTAGES 3
#define TILE_WORDS (128 * 36)                   // one operand tile (padded)
#define STAGE_WORDS (2 * TILE_WORDS)            // A + B
#define GEMM_SMEM_BYTES (GSTAGES * STAGE_WORDS * 4)

template <int NTOT, int K, bool BN>
__global__ __launch_bounds__(256, 2)
void k_gemm(const float* __restrict__ A, const uint32_t* __restrict__ Bt,
            float* __restrict__ C,
            const float* __restrict__ bnS, const float* __restrict__ bnT,
            float* __restrict__ osum, float* __restrict__ osq) {
    constexpr int NB    = NTOT / 128;           // n-blocks per M-tile
    constexpr int ITERS = K / 32;               // k-tiles per block-tile
    constexpr int TBT   = MTILES * NB;          // total block-tiles
    extern __shared__ uint32_t sm[];
    __shared__ float sS[256], sT[256];
    const int tid  = threadIdx.x;
    const int warp = tid >> 5;
    const int lane = tid & 31;
    const int wm   = warp >> 1;
    const int wn   = warp & 1;
    const int g    = lane >> 2;
    const int tg   = lane & 3;
    const int bid  = blockIdx.x;
    const int gx   = gridDim.x;

    int frow[4], fcol[4];
    #pragma unroll
    for (int it = 0; it < 4; it++) {
        int idx = tid + it * 256;
        frow[it] = idx >> 3;
        fcol[it] = (idx & 7) * 4;
    }

    const int myBT  = (TBT - bid + gx - 1) / gx;    // my block-tiles
    const int total = myBT * ITERS;                 // my flat k-tiles

    auto issue = [&](int flat) {
        if (flat < total) {
            int w  = flat / ITERS;
            int i  = flat - w * ITERS;
            int bt = bid + w * gx;
            int mb = (bt / NB) * 128;
            int nb = (bt % NB) * 128;
            uint32_t* as = sm + (flat % GSTAGES) * STAGE_WORDS;
            uint32_t* bs = as + TILE_WORDS;
            #pragma unroll
            for (int it = 0; it < 4; it++) {
                const float*    ga = A  + (size_t)(mb + frow[it]) * K + i * 32 + fcol[it];
                const uint32_t* gb = Bt + (size_t)(nb + frow[it]) * K + i * 32 + fcol[it];
                uint32_t da = (uint32_t)__cvta_generic_to_shared(as + frow[it] * 36 + fcol[it]);
                uint32_t db = (uint32_t)__cvta_generic_to_shared(bs + frow[it] * 36 + fcol[it]);
                asm volatile("cp.async.cg.shared.global [%0], [%1], 16;" :: "r"(da), "l"(ga));
                asm volatile("cp.async.cg.shared.global [%0], [%1], 16;" :: "r"(db), "l"(gb));
            }
        }
        asm volatile("cp.async.commit_group;");
    };

    issue(0);
    issue(1);

    if (BN) {
        for (int c = tid; c < K; c += 256) { sS[c] = bnS[c]; sT[c] = bnT[c]; }
        __syncthreads();                     // sS/sT visible before first cvt
    }

    float acc[2][8][4] = {};

    for (int t = 0; t < total; t++) {
        const int w  = t / ITERS;
        const int i  = t - w * ITERS;
        const int bt = bid + w * gx;
        const int mb = (bt / NB) * 128;
        const int nb = (bt % NB) * 128;

        asm volatile("cp.async.wait_group 1;");   // groups <= t complete

        // --- convert this thread's own staged A words (self-visibility ok) -
        uint32_t* as = sm + (t % GSTAGES) * STAGE_WORDS;
        #pragma unroll
        for (int it = 0; it < 4; it++) {
            uint32_t* p = as + frow[it] * 36 + fcol[it];
            float4 v = *reinterpret_cast<const float4*>(p);
            if (BN) {
                if (mb + frow[it] < N_NODES) {
                    int kk = i * 32 + fcol[it];
                    v.x = fmaxf(fmaf(v.x, sS[kk + 0], sT[kk + 0]), 0.f);
                    v.y = fmaxf(fmaf(v.y, sS[kk + 1], sT[kk + 1]), 0.f);
                    v.z = fmaxf(fmaf(v.z, sS[kk + 2], sT[kk + 2]), 0.f);
                    v.w = fmaxf(fmaf(v.w, sS[kk + 3], sT[kk + 3]), 0.f);
                } else {
                    v = make_float4(0.f, 0.f, 0.f, 0.f);
                }
            }
            uint4 q;
            q.x = f2tf32(v.x); q.y = f2tf32(v.y);
            q.z = f2tf32(v.z); q.w = f2tf32(v.w);
            *reinterpret_cast<uint4*>(p) = q;
        }

        __syncthreads();   // converts visible; stage (t-1)%3 readers retired

        issue(t + 2);      // overwrites stage (t+2)%3 == (t-1)%3: safe

        const uint32_t* bs = as + TILE_WORDS;
        #pragma unroll
        for (int ks = 0; ks < 4; ks++) {
            const int kc = ks * 8;
            uint32_t af[2][4];
            #pragma unroll
            for (int ii = 0; ii < 2; ii++) {
                int r = wm * 32 + ii * 16 + g;
                af[ii][0] = as[r * 36 + kc + tg];
                af[ii][1] = as[(r + 8) * 36 + kc + tg];
                af[ii][2] = as[r * 36 + kc + tg + 4];
                af[ii][3] = as[(r + 8) * 36 + kc + tg + 4];
            }
            #pragma unroll
            for (int j = 0; j < 8; j++) {
                int n = wn * 64 + j * 8 + g;
                uint32_t b0 = bs[n * 36 + kc + tg];
                uint32_t b1 = bs[n * 36 + kc + tg + 4];
                asm volatile(
                    "mma.sync.aligned.m16n8k8.row.col.f32.tf32.tf32.f32 "
                    "{%0,%1,%2,%3}, {%4,%5,%6,%7}, {%8,%9}, {%0,%1,%2,%3};"
                    : "+f"(acc[0][j][0]), "+f"(acc[0][j][1]),
                      "+f"(acc[0][j][2]), "+f"(acc[0][j][3])
                    : "r"(af[0][0]), "r"(af[0][1]), "r"(af[0][2]), "r"(af[0][3]),
                      "r"(b0), "r"(b1));
                asm volatile(
                    "mma.sync.aligned.m16n8k8.row.col.f32.tf32.tf32.f32 "
                    "{%0,%1,%2,%3}, {%4,%5,%6,%7}, {%8,%9}, {%0,%1,%2,%3};"
                    : "+f"(acc[1][j][0]), "+f"(acc[1][j][1]),
                      "+f"(acc[1][j][2]), "+f"(acc[1][j][3])
                    : "r"(af[1][0]), "r"(af[1][1]), "r"(af[1][2]), "r"(af[1][3]),
                      "r"(b0), "r"(b1));
            }
        }

        if (i == ITERS - 1) {
            // ---- block-tile epilogue: store C + fused column stats --------
            #pragma unroll
            for (int ii = 0; ii < 2; ii++) {
                int r0 = mb + wm * 32 + ii * 16 + g;
                int r1 = r0 + 8;
                #pragma unroll
                for (int j = 0; j < 8; j++) {
                    int c0 = nb + wn * 64 + j * 8 + tg * 2;
                    *reinterpret_cast<float2*>(C + (size_t)r0 * NTOT + c0) =
                        make_float2(acc[0][j][0], acc[0][j][1]);
                    *reinterpret_cast<float2*>(C + (size_t)r1 * NTOT + c0) =
                        make_float2(acc[0][j][2], acc[0][j][3]);
                    (void)ii;
                }
                // note: ii indexes acc below; split loops to keep addressing simple
                break;
            }
            #pragma unroll
            for (int j = 0; j < 8; j++) {
                int r0 = mb + wm * 32 + 16 + g;     // ii = 1 rows
                int r1 = r0 + 8;
                int c0 = nb + wn * 64 + j * 8 + tg * 2;
                *reinterpret_cast<float2*>(C + (size_t)r0 * NTOT + c0) =
                    make_float2(acc[1][j][0], acc[1][j][1]);
                *reinterpret_cast<float2*>(C + (size_t)r1 * NTOT + c0) =
                    make_float2(acc[1][j][2], acc[1][j][3]);
            }
            #pragma unroll
            for (int j = 0; j < 8; j++) {
                #pragma unroll
                for (int q = 0; q < 2; q++) {
                    float a0 = acc[0][j][q],     a1 = acc[0][j][q + 2];
                    float a2 = acc[1][j][q],     a3 = acc[1][j][q + 2];
                    float s  = a0 + a1 + a2 + a3;
                    float ss = a0 * a0 + a1 * a1 + a2 * a2 + a3 * a3;
                    #pragma unroll
                    for (int o = 4; o < 32; o <<= 1) {
                        s  += __shfl_xor_sync(0xffffffffu, s,  o);
                        ss += __shfl_xor_sync(0xffffffffu, ss, o);
                    }
                    if (g == 0) {
                        int c = nb + wn * 64 + j * 8 + tg * 2 + q;
                        atomicAdd(&osum[c], s);
                        atomicAdd(&osq[c], ss);
                    }
                }
            }
            #pragma unroll
            for (int ii = 0; ii < 2; ii++)
                #pragma unroll
                for (int j = 0; j < 8; j++)
                    #pragma unroll
                    for (int q = 0; q < 4; q++) acc[ii][j][q] = 0.f;
        }
    }
}

// ---------------- BN params ------------------------------------------------

__global__ void k_bn_params(const float* __restrict__ sum,
                            const float* __restrict__ sq,
                            const float* __restrict__ gam,
                            const float* __restrict__ bet,
                            int C, float* __restrict__ oS, float* __restrict__ oT) {
    int c = threadIdx.x;
    if (c >= C) return;
    const float invN = 1.0f / (float)N_NODES;
    float mean = sum[c] * invN;
    float var  = sq[c] * invN - mean * mean;
    float s = gam[c] * rsqrtf(var + 1e-5f);
    oS[c] = s;
    oT[c] = bet[c] - mean * s;
}

// out = relu(bn2(X2)), X2 lives in g_H0 (f32, raw GEMM2 output)
__global__ void k_final(const float* __restrict__ s2,
                        const float* __restrict__ t2,
                        float* __restrict__ out) {
    int idx = blockIdx.x * blockDim.x + threadIdx.x;
    if (idx >= N_NODES * (DIM_D / 4)) return;
    int c0 = (idx & 31) * 4;
    float4 v = reinterpret_cast<const float4*>(g_H0)[idx];
    float4 o;
    o.x = fmaxf(fmaf(v.x, s2[c0 + 0], t2[c0 + 0]), 0.f);
    o.y = fmaxf(fmaf(v.y, s2[c0 + 1], t2[c0 + 1]), 0.f);
    o.z = fmaxf(fmaf(v.z, s2[c0 + 2], t2[c0 + 2]), 0.f);
    o.w = fmaxf(fmaf(v.w, s2[c0 + 3], t2[c0 + 3]), 0.f);
    reinterpret_cast<float4*>(out)[idx] = o;
}

// ---------------- launch ----------------------------------------------------

extern "C" void kernel_launch(void* const* d_in, const int* in_sizes, int n_in,
                              void* d_out, int out_size) {
    const float* node_rep  = (const float*)d_in[0];
    const float* edge_attr = (const float*)d_in[1];
    const float* degree    = (const float*)d_in[2];
    const float* eps       = (const float*)d_in[3];
    const float* W1        = (const float*)d_in[4];
    const float* gam1      = (const float*)d_in[5];
    const float* bet1      = (const float*)d_in[6];
    const float* W2        = (const float*)d_in[7];
    const float* gam2      = (const float*)d_in[8];
    const float* bet2      = (const float*)d_in[9];
    const int*   src       = (const int*)d_in[10];
    const int*   dst       = (const int*)d_in[11];
    float* out = (float*)d_out;

    float *pH0, *pX1, *psum1, *psq1, *psum2, *psq2, *ps1, *pt1, *ps2, *pt2;
    uint32_t *pW1t, *pW2t;
    cudaGetSymbolAddress((void**)&pH0, g_H0);
    cudaGetSymbolAddress((void**)&pX1, g_X1);
    cudaGetSymbolAddress((void**)&pW1t, g_W1t);
    cudaGetSymbolAddress((void**)&pW2t, g_W2t);
    cudaGetSymbolAddress((void**)&psum1, g_sum1);
    cudaGetSymbolAddress((void**)&psq1, g_sq1);
    cudaGetSymbolAddress((void**)&psum2, g_sum2);
    cudaGetSymbolAddress((void**)&psq2, g_sq2);
    cudaGetSymbolAddress((void**)&ps1, g_s1);
    cudaGetSymbolAddress((void**)&pt1, g_t1);
    cudaGetSymbolAddress((void**)&ps2, g_s2);
    cudaGetSymbolAddress((void**)&pt2, g_t2);

    cudaFuncSetAttribute((const void*)k_gemm<256, 128, false>,
                         cudaFuncAttributeMaxDynamicSharedMemorySize, GEMM_SMEM_BYTES);
    cudaFuncSetAttribute((const void*)k_gemm<128, 256, true>,
                         cudaFuncAttributeMaxDynamicSharedMemorySize, GEMM_SMEM_BYTES);

    k_init<<<(MPAD * (DIM_D / 4) + 255) / 256, 256>>>(node_rep, degree, eps, W1, W2);
    k_edge_scatter<<<N_EDGES / 8, 256>>>(node_rep, edge_attr, src, dst);

    k_gemm<256, 128, false><<<GEMM_GRID, 256, GEMM_SMEM_BYTES>>>(
        (const float*)pH0, pW1t, pX1, nullptr, nullptr, psum1, psq1);
    k_bn_params<<<1, DIM_H>>>(psum1, psq1, gam1, bet1, DIM_H, ps1, pt1);

    k_gemm<128, 256, true><<<GEMM_GRID, 256, GEMM_SMEM_BYTES>>>(
        (const float*)pX1, pW2t, pH0, ps1, pt1, psum2, psq2);
    k_bn_params<<<1, DIM_D>>>(psum2, psq2, gam2, bet2, DIM_D, ps2, pt2);

    k_final<<<(N_NODES * (DIM_D / 4) + 255) / 256, 256>>>(ps2, pt2, out);
}

// round 15
// speedup vs baseline: 1.3583x; 1.3583x over previous
#include <cuda_runtime.h>
#include <cstdint>
#include <cstddef>

#define N_NODES 100000
#define MPAD    100096            // 782 * 128
#define N_EDGES 600000
#define DIM_D 128
#define DIM_H 256

// ---------------- scratch (device globals: no allocation allowed) ----------
__device__ __align__(256) float g_H0[(size_t)MPAD * DIM_D];   // h (agg, f32); reused as X2
__device__ __align__(256) float g_X1[(size_t)MPAD * DIM_H];   // layer-1 raw output (f32)
__device__ __align__(256) uint32_t g_W1t[DIM_H * DIM_D];      // tf32 weights
__device__ __align__(256) uint32_t g_W2t[DIM_D * DIM_H];
__device__ float g_sum1[DIM_H];
__device__ float g_sq1[DIM_H];
__device__ float g_sum2[DIM_D];
__device__ float g_sq2[DIM_D];
__device__ float g_s1[DIM_H];
__device__ float g_t1[DIM_H];
__device__ float g_s2[DIM_D];
__device__ float g_t2[DIM_D];

__device__ __forceinline__ uint32_t f2tf32(float x) {
    uint32_t r;
    asm("cvt.rna.tf32.f32 %0, %1;" : "=r"(r) : "f"(x));
    return r;
}

// ---------------- graph aggregation ----------------------------------------
// Algebraic note: node_new contains deg(n)*nr[n] (each incident edge adds
// nr[self] once per endpoint slot), cancelling the -deg*nr in the residual:
//   h[n] = (1+eps)*nr[n] + sum_incident (nr[other] + ea)
// (self-loop check: both forms give 4*nr + 2*ea). So init uses (1+eps) only
// and the per-edge scatter adds nr[other]+ea -- no degree array anywhere.

// H0[n,:] = (1+eps) * node_rep[n,:]; pad rows = 0; zero stats; weights->tf32
__global__ void k_init(const float* __restrict__ nr,
                       const float* __restrict__ eps,
                       const float* __restrict__ W1,
                       const float* __restrict__ W2) {
    int gidx = blockIdx.x * blockDim.x + threadIdx.x;
    if (blockIdx.x == 0) {
        int t = threadIdx.x;
        if (t < DIM_H) { g_sum1[t] = 0.f; g_sq1[t] = 0.f; }
        if (t < DIM_D) { g_sum2[t] = 0.f; g_sq2[t] = 0.f; }
    }
    if (gidx < DIM_H * DIM_D) {
        g_W1t[gidx] = f2tf32(W1[gidx]);
        g_W2t[gidx] = f2tf32(W2[gidx]);
    }
    if (gidx >= MPAD * (DIM_D / 4)) return;
    int row = gidx >> 5;                               // 32 float4 per row
    float4 o = make_float4(0.f, 0.f, 0.f, 0.f);
    if (row < N_NODES) {
        float c = 1.0f + eps[0];
        float4 v = reinterpret_cast<const float4*>(nr)[gidx];
        o = make_float4(c * v.x, c * v.y, c * v.z, c * v.w);
    }
    reinterpret_cast<float4*>(g_H0)[gidx] = o;
}

__device__ __forceinline__ void red_add_v4(float* addr, float4 v) {
    asm volatile("red.global.add.v4.f32 [%0], {%1,%2,%3,%4};"
                 :: "l"(addr), "f"(v.x), "f"(v.y), "f"(v.z), "f"(v.w)
                 : "memory");
}

// TWO edges per warp: batches 6 independent LDG.128 + 4 RED.128 per warp
// (doubled front-batched MLP vs 1 edge/warp; halved index-load overhead).
// H0[s] += nr[d]+ea ; H0[d] += nr[s]+ea   (degree term cancelled, see above)
// edge_attr is a one-shot 307MB stream -> evict-streaming load keeps the
// L2-resident node tables (nr + H0) hot for the gathers/atomics.
__global__ void k_edge_scatter(const float* __restrict__ nr,
                               const float* __restrict__ ea,
                               const int* __restrict__ src,
                               const int* __restrict__ dst) {
    int w = blockIdx.x * 8 + (threadIdx.x >> 5);       // warp id
    int e0 = w * 2;
    if (e0 >= N_EDGES) return;
    int lane = threadIdx.x & 31;
    int2 s2 = *reinterpret_cast<const int2*>(src + e0);   // src[e0], src[e0+1]
    int2 d2 = *reinterpret_cast<const int2*>(dst + e0);
    const float4* nrv = reinterpret_cast<const float4*>(nr);
    float4 a0 = __ldg(nrv + (size_t)s2.x * 32 + lane);
    float4 b0 = __ldg(nrv + (size_t)d2.x * 32 + lane);
    float4 a1 = __ldg(nrv + (size_t)s2.y * 32 + lane);
    float4 b1 = __ldg(nrv + (size_t)d2.y * 32 + lane);
    float4 c0 = __ldcs(reinterpret_cast<const float4*>(ea) + (size_t)e0 * 32 + lane);
    float4 c1 = __ldcs(reinterpret_cast<const float4*>(ea) + (size_t)(e0 + 1) * 32 + lane);

    float4 ms0 = make_float4(b0.x + c0.x, b0.y + c0.y, b0.z + c0.z, b0.w + c0.w);
    float4 md0 = make_float4(a0.x + c0.x, a0.y + c0.y, a0.z + c0.z, a0.w + c0.w);
    float4 ms1 = make_float4(b1.x + c1.x, b1.y + c1.y, b1.z + c1.z, b1.w + c1.w);
    float4 md1 = make_float4(a1.x + c1.x, a1.y + c1.y, a1.z + c1.z, a1.w + c1.w);

    red_add_v4(g_H0 + (size_t)s2.x * DIM_D + lane * 4, ms0);
    red_add_v4(g_H0 + (size_t)d2.x * DIM_D + lane * 4, md0);
    red_add_v4(g_H0 + (size_t)s2.y * DIM_D + lane * 4, ms1);
    red_add_v4(g_H0 + (size_t)d2.y * DIM_D + lane * 4, md1);
}

// ---------------- tf32 tensor-core GEMM, cp.async 3-stage pipeline ---------
// (verbatim R8 structure: best measured GEMM at 92.5us; wave-launched,
//  2 CTA/SM, ONE __syncthreads per K-tile)
// C[m,n] = sum_k A[m,k] * B[n,k].
// A raw f32 via cp.async; each thread converts IN-SMEM exactly the words its
// own cp.async staged (own-group visibility needs only wait_group, no barrier).
// BN==true additionally applies y=relu(x*s+t) and zeroes pad rows.
//   wait_group 1 -> cvt(own words, stage i) -> barrier -> issue(i+2) -> mma(i)
// The barrier also retires all readers of stage (i-1) before issue(i+2)
// overwrites it ((i+2)%3 == (i-1)%3).
// Block 128x128, BK=32, 8 warps 4(M)x2(N), warp tile 32x64.
// Epilogue: store C (f32) + atomically accumulate per-column sum / sum-sq.

#define GSTAGES 3
#define TILE_WORDS (128 * 36)                   // one operand tile (padded)
#define STAGE_WORDS (2 * TILE_WORDS)            // A + B
#define GEMM_SMEM_BYTES (GSTAGES * STAGE_WORDS * 4)

template <bool BN>
__global__ __launch_bounds__(256, 2)
void k_gemm(const float* __restrict__ A, const uint32_t* __restrict__ Bt,
            float* __restrict__ C, int Ntot, int K,
            const float* __restrict__ bnS, const float* __restrict__ bnT,
            float* __restrict__ osum, float* __restrict__ osq) {
    extern __shared__ uint32_t sm[];
    __shared__ float sS[DIM_H], sT[DIM_H];
    const int tid  = threadIdx.x;
    const int warp = tid >> 5;
    const int lane = tid & 31;
    const int wm   = warp >> 1;
    const int wn   = warp & 1;
    const int g    = lane >> 2;
    const int tg   = lane & 3;
    const int mbase = blockIdx.y * 128;
    const int nbase = blockIdx.x * 128;

    int frow[4], fcol[4];
    #pragma unroll
    for (int it = 0; it < 4; it++) {
        int idx = tid + it * 256;
        frow[it] = idx >> 3;
        fcol[it] = (idx & 7) * 4;
    }
    const int iters = K >> 5;

    float acc[2][8][4] = {};

    auto issue = [&](int i) {
        uint32_t* as = sm + (i % GSTAGES) * STAGE_WORDS;
        uint32_t* bs = as + TILE_WORDS;
        #pragma unroll
        for (int it = 0; it < 4; it++) {
            const float*    ga = A  + (size_t)(mbase + frow[it]) * K + i * 32 + fcol[it];
            const uint32_t* gb = Bt + (size_t)(nbase + frow[it]) * K + i * 32 + fcol[it];
            uint32_t da = (uint32_t)__cvta_generic_to_shared(as + frow[it] * 36 + fcol[it]);
            uint32_t db = (uint32_t)__cvta_generic_to_shared(bs + frow[it] * 36 + fcol[it]);
            asm volatile("cp.async.cg.shared.global [%0], [%1], 16;" :: "r"(da), "l"(ga));
            asm volatile("cp.async.cg.shared.global [%0], [%1], 16;" :: "r"(db), "l"(gb));
        }
        asm volatile("cp.async.commit_group;");
    };

    issue(0);
    issue(1);

    if (BN) {
        for (int c = tid; c < K; c += 256) { sS[c] = bnS[c]; sT[c] = bnT[c]; }
        __syncthreads();                     // sS/sT visible before first cvt
    }

    for (int i = 0; i < iters; i++) {
        asm volatile("cp.async.wait_group 1;");   // groups <= i complete

        // --- convert this thread's own staged A words (self-visibility ok) -
        uint32_t* as = sm + (i % GSTAGES) * STAGE_WORDS;
        #pragma unroll
        for (int it = 0; it < 4; it++) {
            uint32_t* p = as + frow[it] * 36 + fcol[it];
            float4 v = *reinterpret_cast<const float4*>(p);
            if (BN) {
                if (mbase + frow[it] < N_NODES) {
                    int kk = i * 32 + fcol[it];
                    v.x = fmaxf(fmaf(v.x, sS[kk + 0], sT[kk + 0]), 0.f);
                    v.y = fmaxf(fmaf(v.y, sS[kk + 1], sT[kk + 1]), 0.f);
                    v.z = fmaxf(fmaf(v.z, sS[kk + 2], sT[kk + 2]), 0.f);
                    v.w = fmaxf(fmaf(v.w, sS[kk + 3], sT[kk + 3]), 0.f);
                } else {
                    v = make_float4(0.f, 0.f, 0.f, 0.f);
                }
            }
            uint4 q;
            q.x = f2tf32(v.x); q.y = f2tf32(v.y);
            q.z = f2tf32(v.z); q.w = f2tf32(v.w);
            *reinterpret_cast<uint4*>(p) = q;
        }

        __syncthreads();   // converts visible to all; prior-stage readers done

        if (i + 2 < iters) issue(i + 2);
        else asm volatile("cp.async.commit_group;");   // keep group count in step

        const uint32_t* bs = as + TILE_WORDS;
        #pragma unroll
        for (int ks = 0; ks < 4; ks++) {
            const int kc = ks * 8;
            uint32_t af[2][4];
            #pragma unroll
            for (int ii = 0; ii < 2; ii++) {
                int r = wm * 32 + ii * 16 + g;
                af[ii][0] = as[r * 36 + kc + tg];
                af[ii][1] = as[(r + 8) * 36 + kc + tg];
                af[ii][2] = as[r * 36 + kc + tg + 4];
                af[ii][3] = as[(r + 8) * 36 + kc + tg + 4];
            }
            #pragma unroll
            for (int j = 0; j < 8; j++) {
                int n = wn * 64 + j * 8 + g;
                uint32_t b0 = bs[n * 36 + kc + tg];
                uint32_t b1 = bs[n * 36 + kc + tg + 4];
                asm volatile(
                    "mma.sync.aligned.m16n8k8.row.col.f32.tf32.tf32.f32 "
                    "{%0,%1,%2,%3}, {%4,%5,%6,%7}, {%8,%9}, {%0,%1,%2,%3};"
                    : "+f"(acc[0][j][0]), "+f"(acc[0][j][1]),
                      "+f"(acc[0][j][2]), "+f"(acc[0][j][3])
                    : "r"(af[0][0]), "r"(af[0][1]), "r"(af[0][2]), "r"(af[0][3]),
                      "r"(b0), "r"(b1));
                asm volatile(
                    "mma.sync.aligned.m16n8k8.row.col.f32.tf32.tf32.f32 "
                    "{%0,%1,%2,%3}, {%4,%5,%6,%7}, {%8,%9}, {%0,%1,%2,%3};"
                    : "+f"(acc[1][j][0]), "+f"(acc[1][j][1]),
                      "+f"(acc[1][j][2]), "+f"(acc[1][j][3])
                    : "r"(af[1][0]), "r"(af[1][1]), "r"(af[1][2]), "r"(af[1][3]),
                      "r"(b0), "r"(b1));
            }
        }
    }

    // --- store C (no guards: M padded, N multiple of 128) -----------------
    #pragma unroll
    for (int ii = 0; ii < 2; ii++) {
        int r0 = mbase + wm * 32 + ii * 16 + g;
        int r1 = r0 + 8;
        #pragma unroll
        for (int j = 0; j < 8; j++) {
            int c0 = nbase + wn * 64 + j * 8 + tg * 2;
            *reinterpret_cast<float2*>(C + (size_t)r0 * Ntot + c0) =
                make_float2(acc[ii][j][0], acc[ii][j][1]);
            *reinterpret_cast<float2*>(C + (size_t)r1 * Ntot + c0) =
                make_float2(acc[ii][j][2], acc[ii][j][3]);
        }
    }

    // --- fused column stats: reduce 32 warp-tile rows, atomic to global ---
    #pragma unroll
    for (int j = 0; j < 8; j++) {
        #pragma unroll
        for (int q = 0; q < 2; q++) {
            float a0 = acc[0][j][q],     a1 = acc[0][j][q + 2];
            float a2 = acc[1][j][q],     a3 = acc[1][j][q + 2];
            float s  = a0 + a1 + a2 + a3;
            float ss = a0 * a0 + a1 * a1 + a2 * a2 + a3 * a3;
            #pragma unroll
            for (int o = 4; o < 32; o <<= 1) {
                s  += __shfl_xor_sync(0xffffffffu, s,  o);
                ss += __shfl_xor_sync(0xffffffffu, ss, o);
            }
            if (g == 0) {
                int c = nbase + wn * 64 + j * 8 + tg * 2 + q;
                atomicAdd(&osum[c], s);
                atomicAdd(&osq[c], ss);
            }
        }
    }
}

// ---------------- BN params ------------------------------------------------

__global__ void k_bn_params(const float* __restrict__ sum,
                            const float* __restrict__ sq,
                            const float* __restrict__ gam,
                            const float* __restrict__ bet,
                            int C, float* __restrict__ oS, float* __restrict__ oT) {
    int c = threadIdx.x;
    if (c >= C) return;
    const float invN = 1.0f / (float)N_NODES;
    float mean = sum[c] * invN;
    float var  = sq[c] * invN - mean * mean;
    float s = gam[c] * rsqrtf(var + 1e-5f);
    oS[c] = s;
    oT[c] = bet[c] - mean * s;
}

// out = relu(bn2(X2)), X2 lives in g_H0 (f32, raw GEMM2 output)
__global__ void k_final(const float* __restrict__ s2,
                        const float* __restrict__ t2,
                        float* __restrict__ out) {
    int idx = blockIdx.x * blockDim.x + threadIdx.x;
    if (idx >= N_NODES * (DIM_D / 4)) return;
    int c0 = (idx & 31) * 4;
    float4 v = reinterpret_cast<const float4*>(g_H0)[idx];
    float4 o;
    o.x = fmaxf(fmaf(v.x, s2[c0 + 0], t2[c0 + 0]), 0.f);
    o.y = fmaxf(fmaf(v.y, s2[c0 + 1], t2[c0 + 1]), 0.f);
    o.z = fmaxf(fmaf(v.z, s2[c0 + 2], t2[c0 + 2]), 0.f);
    o.w = fmaxf(fmaf(v.w, s2[c0 + 3], t2[c0 + 3]), 0.f);
    reinterpret_cast<float4*>(out)[idx] = o;
}

// ---------------- launch ----------------------------------------------------

extern "C" void kernel_launch(void* const* d_in, const int* in_sizes, int n_in,
                              void* d_out, int out_size) {
    const float* node_rep  = (const float*)d_in[0];
    const float* edge_attr = (const float*)d_in[1];
    const float* eps       = (const float*)d_in[3];
    const float* W1        = (const float*)d_in[4];
    const float* gam1      = (const float*)d_in[5];
    const float* bet1      = (const float*)d_in[6];
    const float* W2        = (const float*)d_in[7];
    const float* gam2      = (const float*)d_in[8];
    const float* bet2      = (const float*)d_in[9];
    const int*   src       = (const int*)d_in[10];
    const int*   dst       = (const int*)d_in[11];
    float* out = (float*)d_out;

    float *pH0, *pX1, *psum1, *psq1, *psum2, *psq2, *ps1, *pt1, *ps2, *pt2;
    uint32_t *pW1t, *pW2t;
    cudaGetSymbolAddress((void**)&pH0, g_H0);
    cudaGetSymbolAddress((void**)&pX1, g_X1);
    cudaGetSymbolAddress((void**)&pW1t, g_W1t);
    cudaGetSymbolAddress((void**)&pW2t, g_W2t);
    cudaGetSymbolAddress((void**)&psum1, g_sum1);
    cudaGetSymbolAddress((void**)&psq1, g_sq1);
    cudaGetSymbolAddress((void**)&psum2, g_sum2);
    cudaGetSymbolAddress((void**)&psq2, g_sq2);
    cudaGetSymbolAddress((void**)&ps1, g_s1);
    cudaGetSymbolAddress((void**)&pt1, g_t1);
    cudaGetSymbolAddress((void**)&ps2, g_s2);
    cudaGetSymbolAddress((void**)&pt2, g_t2);

    cudaFuncSetAttribute(k_gemm<false>, cudaFuncAttributeMaxDynamicSharedMemorySize,
                         GEMM_SMEM_BYTES);
    cudaFuncSetAttribute(k_gemm<true>, cudaFuncAttributeMaxDynamicSharedMemorySize,
                         GEMM_SMEM_BYTES);

    k_init<<<(MPAD * (DIM_D / 4) + 255) / 256, 256>>>(node_rep, eps, W1, W2);
    k_edge_scatter<<<(N_EDGES / 2 + 7) / 8, 256>>>(node_rep, edge_attr, src, dst);

    dim3 grid1(DIM_H / 128, MPAD / 128);   // x fastest -> A tile L2 reuse
    k_gemm<false><<<grid1, 256, GEMM_SMEM_BYTES>>>((const float*)pH0, pW1t, pX1,
                                                   DIM_H, DIM_D, nullptr, nullptr,
                                                   psum1, psq1);
    k_bn_params<<<1, DIM_H>>>(psum1, psq1, gam1, bet1, DIM_H, ps1, pt1);

    dim3 grid2(DIM_D / 128, MPAD / 128);
    k_gemm<true><<<grid2, 256, GEMM_SMEM_BYTES>>>((const float*)pX1, pW2t, pH0,
                                                  DIM_D, DIM_H, ps1, pt1,
                                                  psum2, psq2);
    k_bn_params<<<1, DIM_D>>>(psum2, psq2, gam2, bet2, DIM_D, ps2, pt2);

    k_final<<<(N_NODES * (DIM_D / 4) + 255) / 256, 256>>>(ps2, pt2, out);
}